// round 15
// baseline (speedup 1.0000x reference)
#include <cuda_runtime.h>
#include <cuda_fp16.h>
#include <mma.h>
#include <cstddef>
#include <cstdint>
#include <type_traits>

using namespace nvcuda;

#define BB 2
#define SS 2048
#define DD 1024
#define HH 16
#define DKK 64

#define NACT ((size_t)BB * SS * DD)     // 4,194,304
#define NW   ((size_t)DD * DD)          // 1,048,576

// ---- scratch (device globals) ----
__device__ half g_qh[NACT], g_kh[NACT], g_vh[NACT];
__device__ half g_Wqh[NW], g_Wkh[NW], g_Wvh[NW];
__device__ half g_Woh[NW], g_Wol[NW];
__device__ half g_yqh[NACT], g_ykh[NACT], g_yvh[NACT];
__device__ half g_ch[NACT], g_cl[NACT];
__device__ half g_es[(size_t)BB * HH * SS * SS];       // un-normalized exp(scores), fp16
__device__ float g_iz[(size_t)BB * HH * SS];           // 1/Z per row

// ---------------------------------------------------------------------------
__device__ __forceinline__ void cp_async16(void* smem_dst, const void* gmem_src) {
    uint32_t s = (uint32_t)__cvta_generic_to_shared(smem_dst);
    asm volatile("cp.async.cg.shared.global [%0], [%1], 16;" :: "r"(s), "l"(gmem_src) : "memory");
}
__device__ __forceinline__ void cp_commit() {
    asm volatile("cp.async.commit_group;" ::: "memory");
}
__device__ __forceinline__ void cp_wait1() {
    asm volatile("cp.async.wait_group 1;" ::: "memory");
}
__device__ __forceinline__ void cp_wait0() {
    asm volatile("cp.async.wait_group 0;" ::: "memory");
}

// ---------------------------------------------------------------------------
// fp32 -> fp16 convert (hi only), 3 tensors batched via blockIdx.y
// ---------------------------------------------------------------------------
__global__ void conv3_v4(const float4* __restrict__ x0, const float4* __restrict__ x1,
                         const float4* __restrict__ x2,
                         uint2* __restrict__ y0, uint2* __restrict__ y1,
                         uint2* __restrict__ y2, int n4)
{
    const int z = blockIdx.y;
    const float4* x = (z == 0) ? x0 : (z == 1) ? x1 : x2;
    uint2* y = (z == 0) ? y0 : (z == 1) ? y1 : y2;
    int i = blockIdx.x * blockDim.x + threadIdx.x;
    if (i < n4) {
        const float4 v = x[i];
        __half2 h01 = __floats2half2_rn(v.x, v.y);
        __half2 h23 = __floats2half2_rn(v.z, v.w);
        uint2 u; memcpy(&u, &h01, 4); memcpy(((char*)&u) + 4, &h23, 4);
        y[i] = u;
    }
}

// fp32 -> (hi, lo) split (Wo only)
__global__ void split_f32_v4(const float4* __restrict__ x, uint2* __restrict__ hi,
                             uint2* __restrict__ lo, int n4)
{
    int i = blockIdx.x * blockDim.x + threadIdx.x;
    if (i < n4) {
        const float4 v = x[i];
        __half2 h01 = __floats2half2_rn(v.x, v.y);
        __half2 h23 = __floats2half2_rn(v.z, v.w);
        uint2 uh; memcpy(&uh, &h01, 4); memcpy(((char*)&uh) + 4, &h23, 4);
        hi[i] = uh;
        __half2 l01 = __floats2half2_rn(v.x - __low2float(h01), v.y - __high2float(h01));
        __half2 l23 = __floats2half2_rn(v.z - __low2float(h23), v.w - __high2float(h23));
        uint2 ul; memcpy(&ul, &l01, 4); memcpy(((char*)&ul) + 4, &l23, 4);
        lo[i] = ul;
    }
}

// ---------------------------------------------------------------------------
// Pure-fp16 projection GEMM, 3 projections batched via blockIdx.z.
// ---------------------------------------------------------------------------
__global__ __launch_bounds__(256) void proj_h(
    const half* __restrict__ A0, const half* __restrict__ A1, const half* __restrict__ A2,
    const half* __restrict__ B0, const half* __restrict__ B1, const half* __restrict__ B2,
    const float* __restrict__ b0, const float* __restrict__ b1, const float* __restrict__ b2,
    half* __restrict__ C0, half* __restrict__ C1, half* __restrict__ C2)
{
    constexpr int BM = 128, BN = 128, BK = 32;
    constexpr int LDA = BK + 8;
    constexpr int ASZ = BM * LDA;
    constexpr int BSZ = BN * LDA;
    constexpr int LDST = 20;

    extern __shared__ __align__(16) char smem_raw[];
    half* Ash = (half*)smem_raw;
    half* Bsh = Ash + 2 * ASZ;
    float* stage = (float*)(Bsh + 2 * BSZ);

    const int z = blockIdx.z;
    const half* A = (z == 0) ? A0 : (z == 1) ? A1 : A2;
    const half* B = (z == 0) ? B0 : (z == 1) ? B1 : B2;
    const float* bias = (z == 0) ? b0 : (z == 1) ? b1 : b2;
    half* C = (z == 0) ? C0 : (z == 1) ? C1 : C2;

    const int tm = blockIdx.y * BM;
    const int tn = blockIdx.x * BN;
    const int tid = threadIdx.x;
    const int wid = tid >> 5, lane = tid & 31;
    const int wm0 = (wid >> 1) * 32;
    const int wn0 = (wid & 1) * 64;

    auto load_stage = [&](int st, int k0) {
        half* ah = Ash + st * ASZ;
        half* bh = Bsh + st * BSZ;
#pragma unroll
        for (int i = tid; i < BM * (BK / 8); i += 256) {
            const int r = i >> 2, q = i & 3;
            cp_async16(&ah[r * LDA + q * 8], A + (size_t)(tm + r) * DD + k0 + q * 8);
            cp_async16(&bh[r * LDA + q * 8], B + (size_t)(tn + r) * DD + k0 + q * 8);
        }
    };

    wmma::fragment<wmma::matrix_a, 16, 16, 16, half, wmma::row_major> fa;
    wmma::fragment<wmma::matrix_b, 16, 16, 16, half, wmma::col_major> fb;
    wmma::fragment<wmma::accumulator, 16, 16, 16, float> acc[2][4];

#pragma unroll
    for (int i = 0; i < 2; i++)
#pragma unroll
        for (int j = 0; j < 4; j++) wmma::fill_fragment(acc[i][j], 0.0f);

    const int nIter = DD / BK;
    load_stage(0, 0);
    cp_commit();

    for (int it = 0; it < nIter; it++) {
        if (it + 1 < nIter) {
            load_stage((it + 1) & 1, (it + 1) * BK);
            cp_commit();
            cp_wait1();
        } else {
            cp_wait0();
        }
        __syncthreads();

        const half* ah = Ash + (it & 1) * ASZ;
        const half* bh = Bsh + (it & 1) * BSZ;

#pragma unroll
        for (int ks = 0; ks < 2; ks++) {
#pragma unroll
            for (int i = 0; i < 2; i++) {
                wmma::load_matrix_sync(fa, &ah[(wm0 + i * 16) * LDA + ks * 16], LDA);
#pragma unroll
                for (int j = 0; j < 4; j++) {
                    wmma::load_matrix_sync(fb, &bh[(wn0 + j * 16) * LDA + ks * 16], LDA);
                    wmma::mma_sync(acc[i][j], fa, fb, acc[i][j]);
                }
            }
        }
        __syncthreads();
    }

    float* st = stage + wid * 16 * LDST;
#pragma unroll
    for (int i = 0; i < 2; i++)
#pragma unroll
        for (int j = 0; j < 4; j++) {
            wmma::store_matrix_sync(st, acc[i][j], LDST, wmma::mem_row_major);
            __syncwarp();
            const int r  = lane >> 1;
            const int c0 = (lane & 1) * 8;
            const int gn = tn + wn0 + j * 16 + c0;
            const size_t base = (size_t)(tm + wm0 + i * 16 + r) * DD + gn;
            __half2 hp[4];
#pragma unroll
            for (int k2 = 0; k2 < 4; k2++)
                hp[k2] = __floats2half2_rn(st[r * LDST + c0 + 2 * k2]     + bias[gn + 2 * k2],
                                           st[r * LDST + c0 + 2 * k2 + 1] + bias[gn + 2 * k2 + 1]);
            uint4 u;
            memcpy(&u, hp, 16);
            *reinterpret_cast<uint4*>(C + base) = u;
            __syncwarp();
        }
}
static constexpr size_t SM_PROJ = (size_t)(2 * 128 * 40 + 2 * 128 * 40) * 2 + 8 * 16 * 20 * 4;

// ---------------------------------------------------------------------------
// Output projection: out = (ch+cl) @ (Woh+Wol)^T + bo, fp32 out (3-mma split).
// ---------------------------------------------------------------------------
__global__ __launch_bounds__(256) void gemm_out(
    const half* __restrict__ Ahi, const half* __restrict__ Alo,
    const half* __restrict__ Bhi, const half* __restrict__ Blo,
    const float* __restrict__ bias, float* __restrict__ Cf)
{
    constexpr int BM = 128, BN = 128, BK = 32;
    constexpr int LDA = BK + 8;
    constexpr int ASZ = BM * LDA;
    constexpr int BSZ = BN * LDA;
    constexpr int LDST = 20;

    extern __shared__ __align__(16) char smem_raw[];
    half* p = (half*)smem_raw;
    half* Ash = p;  p += 2 * ASZ;
    half* Asl = p;  p += 2 * ASZ;
    half* Bsh = p;  p += 2 * BSZ;
    half* Bsl = p;  p += 2 * BSZ;
    float* stage = (float*)p;

    const int tm = blockIdx.y * BM;
    const int tn = blockIdx.x * BN;
    const int tid = threadIdx.x;
    const int wid = tid >> 5, lane = tid & 31;
    const int wm0 = (wid >> 1) * 32;
    const int wn0 = (wid & 1) * 64;

    auto load_stage = [&](int st, int k0) {
#pragma unroll
        for (int i = tid; i < BM * (BK / 8); i += 256) {
            const int r = i >> 2, q = i & 3;
            cp_async16(&Ash[st * ASZ + r * LDA + q * 8], Ahi + (size_t)(tm + r) * DD + k0 + q * 8);
            cp_async16(&Asl[st * ASZ + r * LDA + q * 8], Alo + (size_t)(tm + r) * DD + k0 + q * 8);
            cp_async16(&Bsh[st * BSZ + r * LDA + q * 8], Bhi + (size_t)(tn + r) * DD + k0 + q * 8);
            cp_async16(&Bsl[st * BSZ + r * LDA + q * 8], Blo + (size_t)(tn + r) * DD + k0 + q * 8);
        }
    };

    wmma::fragment<wmma::matrix_a, 16, 16, 16, half, wmma::row_major> fa, fal;
    wmma::fragment<wmma::matrix_b, 16, 16, 16, half, wmma::col_major> fb, fbl;
    wmma::fragment<wmma::accumulator, 16, 16, 16, float> acc[2][4];

#pragma unroll
    for (int i = 0; i < 2; i++)
#pragma unroll
        for (int j = 0; j < 4; j++) wmma::fill_fragment(acc[i][j], 0.0f);

    const int nIter = DD / BK;
    load_stage(0, 0);
    cp_commit();

    for (int it = 0; it < nIter; it++) {
        if (it + 1 < nIter) {
            load_stage((it + 1) & 1, (it + 1) * BK);
            cp_commit();
            cp_wait1();
        } else {
            cp_wait0();
        }
        __syncthreads();

        const half* ah = Ash + (it & 1) * ASZ;
        const half* al = Asl + (it & 1) * ASZ;
        const half* bh = Bsh + (it & 1) * BSZ;
        const half* bl = Bsl + (it & 1) * BSZ;

#pragma unroll
        for (int ks = 0; ks < 2; ks++) {
#pragma unroll
            for (int i = 0; i < 2; i++) {
                wmma::load_matrix_sync(fa, &ah[(wm0 + i * 16) * LDA + ks * 16], LDA);
                wmma::load_matrix_sync(fal, &al[(wm0 + i * 16) * LDA + ks * 16], LDA);
#pragma unroll
                for (int j = 0; j < 4; j++) {
                    wmma::load_matrix_sync(fb, &bh[(wn0 + j * 16) * LDA + ks * 16], LDA);
                    wmma::load_matrix_sync(fbl, &bl[(wn0 + j * 16) * LDA + ks * 16], LDA);
                    wmma::mma_sync(acc[i][j], fa, fb, acc[i][j]);
                    wmma::mma_sync(acc[i][j], fal, fb, acc[i][j]);
                    wmma::mma_sync(acc[i][j], fa, fbl, acc[i][j]);
                }
            }
        }
        __syncthreads();
    }

    float* st = stage + wid * 16 * LDST;
#pragma unroll
    for (int i = 0; i < 2; i++)
#pragma unroll
        for (int j = 0; j < 4; j++) {
            wmma::store_matrix_sync(st, acc[i][j], LDST, wmma::mem_row_major);
            __syncwarp();
            const int r  = lane >> 1;
            const int c0 = (lane & 1) * 8;
            const int gn = tn + wn0 + j * 16 + c0;
            const size_t base = (size_t)(tm + wm0 + i * 16 + r) * DD + gn;
            float v[8];
#pragma unroll
            for (int e = 0; e < 8; e++) v[e] = st[r * LDST + c0 + e] + bias[gn + e];
            *reinterpret_cast<float4*>(Cf + base)     = make_float4(v[0], v[1], v[2], v[3]);
            *reinterpret_cast<float4*>(Cf + base + 4) = make_float4(v[4], v[5], v[6], v[7]);
            __syncwarp();
        }
}
static constexpr size_t SM_OUT = (size_t)(4 * 128 * 40 + 4 * 128 * 40) * 2 + 8 * 16 * 20 * 4;

// ---------------------------------------------------------------------------
// Fused attention, 512 threads (16 warps). Per block = (q-tile 128, b*h).
// S warp grid 4x4 (warp tile 32x32); U warp grid 4x4 (warp tile 32x16).
// ---------------------------------------------------------------------------
__global__ __launch_bounds__(512) void fused_attn(
    const half* __restrict__ yq, const half* __restrict__ yk,
    const half* __restrict__ yv,
    half* __restrict__ expsc, float* __restrict__ invz,
    half* __restrict__ ch, half* __restrict__ cl)
{
    constexpr int LDQ = 72;
    constexpr int LDS = 136;
    constexpr int QSZ = 128 * LDQ;
    constexpr int KSZ = 128 * LDQ;
    constexpr int NW16 = 16;

    extern __shared__ __align__(16) char smem_raw[];
    half* Qs  = (half*)smem_raw;
    half* Ks  = Qs + QSZ;
    half* Vs  = Ks + 2 * KSZ;
    half* S16 = Vs + 2 * KSZ;
    float* stage = (float*)(S16 + 128 * LDS);       // 16 warps x 16 x 20
    float* psum  = stage + NW16 * 16 * 20;          // 512
    float* Zs    = psum + 512;                      // 128

    const int qt = blockIdx.x;
    const int bh = blockIdx.y;
    const int b  = bh >> 4, h = bh & 15;
    const int q0 = qt * 128;

    const half* Qg = yq + ((size_t)b * SS + q0) * DD + h * DKK;
    const half* Kg = yk + (size_t)b * SS * DD + h * DKK;
    const half* Vg = yv + (size_t)b * SS * DD + h * DKK;
    half* Erow = expsc + ((size_t)bh * SS + q0) * SS;

    const int tid = threadIdx.x;
    const int wid = tid >> 5, lane = tid & 31;
    // S warp grid 4x4: warp tile 32x32
    const int wm0 = (wid >> 2) * 32;
    const int wn0 = (wid & 3) * 32;
    // U warp grid 4x4: warp tile 32x16
    const int wnU = (wid & 3) * 16;

    if (tid < 128) Zs[tid] = 0.0f;

    auto load_kv = [&](int st, int kt) {
#pragma unroll
        for (int i = tid; i < 1024; i += 512) {
            const int r = i >> 3, c = i & 7;
            cp_async16(&Ks[st * KSZ + r * LDQ + c * 8],
                       Kg + (size_t)(kt * 128 + r) * DD + c * 8);
            cp_async16(&Vs[st * KSZ + r * LDQ + c * 8],
                       Vg + (size_t)(kt * 128 + r) * DD + c * 8);
        }
    };

#pragma unroll
    for (int i = tid; i < 1024; i += 512) {
        const int r = i >> 3, c = i & 7;
        cp_async16(&Qs[r * LDQ + c * 8], Qg + (size_t)r * DD + c * 8);
    }
    load_kv(0, 0);
    cp_commit();

    wmma::fragment<wmma::matrix_a, 16, 16, 16, half, wmma::row_major> fa;
    wmma::fragment<wmma::matrix_b, 16, 16, 16, half, wmma::col_major> fbT;
    wmma::fragment<wmma::matrix_b, 16, 16, 16, half, wmma::row_major> fbN;
    wmma::fragment<wmma::accumulator, 16, 16, 16, float> sacc[2][2];
    wmma::fragment<wmma::accumulator, 16, 16, 16, float> uacc[2];

#pragma unroll
    for (int i = 0; i < 2; i++) wmma::fill_fragment(uacc[i], 0.0f);

    float* st = stage + wid * 16 * 20;

    for (int kt = 0; kt < SS / 128; kt++) {
        if (kt + 1 < SS / 128) {
            load_kv((kt + 1) & 1, kt + 1);
            cp_commit();
            cp_wait1();
        } else {
            cp_wait0();
        }
        __syncthreads();

        const half* Kst = Ks + (kt & 1) * KSZ;
        const half* Vst = Vs + (kt & 1) * KSZ;

        // ---- S = Q @ K^T (128x128, K=64), warp tile 32x32 ----
#pragma unroll
        for (int i = 0; i < 2; i++)
#pragma unroll
            for (int j = 0; j < 2; j++) wmma::fill_fragment(sacc[i][j], 0.0f);
#pragma unroll
        for (int kf = 0; kf < 4; kf++) {
#pragma unroll
            for (int i = 0; i < 2; i++) {
                wmma::load_matrix_sync(fa, &Qs[(wm0 + i * 16) * LDQ + kf * 16], LDQ);
#pragma unroll
                for (int j = 0; j < 2; j++) {
                    wmma::load_matrix_sync(fbT, &Kst[(wn0 + j * 16) * LDQ + kf * 16], LDQ);
                    wmma::mma_sync(sacc[i][j], fa, fbT, sacc[i][j]);
                }
            }
        }

        // ---- exp + fp16 tile in smem ----
#pragma unroll
        for (int i = 0; i < 2; i++)
#pragma unroll
            for (int j = 0; j < 2; j++) {
#pragma unroll
                for (int e = 0; e < 8; e++)
                    sacc[i][j].x[e] = __expf(sacc[i][j].x[e] * 0.125f);
                wmma::store_matrix_sync(st, sacc[i][j], 20, wmma::mem_row_major);
                __syncwarp();
                const int r  = lane >> 1;
                const int c0 = (lane & 1) * 8;
                __half2 hp[4];
#pragma unroll
                for (int k2 = 0; k2 < 4; k2++)
                    hp[k2] = __floats2half2_rn(st[r * 20 + c0 + 2 * k2],
                                               st[r * 20 + c0 + 2 * k2 + 1]);
                uint4 u;
                memcpy(&u, hp, 16);
                *reinterpret_cast<uint4*>(&S16[(wm0 + i * 16 + r) * LDS + wn0 + j * 16 + c0]) = u;
                __syncwarp();
            }
        __syncthreads();   // S16 complete

        // ---- Z partials (4 threads per row) + gmem copy of expS tile ----
        {
            const int r = tid >> 2, quad = tid & 3;
            const __half2* p2 = reinterpret_cast<const __half2*>(&S16[r * LDS + quad * 32]);
            float s = 0.0f;
#pragma unroll
            for (int i = 0; i < 16; i++) {
                const float2 f = __half22float2(p2[i]);
                s += f.x + f.y;
            }
            psum[tid] = s;
        }
#pragma unroll
        for (int idx = tid; idx < 2048; idx += 512) {
            const int r = idx >> 4, c = idx & 15;
            *reinterpret_cast<uint4*>(Erow + (size_t)r * SS + kt * 128 + c * 8) =
                *reinterpret_cast<const uint4*>(&S16[r * LDS + c * 8]);
        }
        __syncthreads();
        if (tid < 128)
            Zs[tid] += psum[4 * tid] + psum[4 * tid + 1] + psum[4 * tid + 2] + psum[4 * tid + 3];

        // ---- U += expS @ V (128x64, K=128), warp tile 32x16 ----
#pragma unroll
        for (int kf = 0; kf < 8; kf++) {
            wmma::load_matrix_sync(fbN, &Vst[(kf * 16) * LDQ + wnU], LDQ);
#pragma unroll
            for (int i = 0; i < 2; i++) {
                wmma::load_matrix_sync(fa, &S16[(wm0 + i * 16) * LDS + kf * 16], LDS);
                wmma::mma_sync(uacc[i], fa, fbN, uacc[i]);
            }
        }
        __syncthreads();
    }

    if (tid < 128) {
        const float iz = 1.0f / Zs[tid];
        Zs[tid] = iz;
        invz[(size_t)bh * SS + q0 + tid] = iz;
    }
    __syncthreads();

#pragma unroll
    for (int i = 0; i < 2; i++) {
        wmma::store_matrix_sync(st, uacc[i], 20, wmma::mem_row_major);
        __syncwarp();
        const int r  = lane >> 1;
        const int c0 = (lane & 1) * 8;
        const int row = wm0 + i * 16 + r;
        const float iz = Zs[row];
        const size_t base = ((size_t)b * SS + q0 + row) * DD + h * DKK + wnU + c0;
        __half2 hh[4], hl[4];
#pragma unroll
        for (int k2 = 0; k2 < 4; k2++) {
            const float v0 = st[r * 20 + c0 + 2 * k2] * iz;
            const float v1 = st[r * 20 + c0 + 2 * k2 + 1] * iz;
            hh[k2] = __floats2half2_rn(v0, v1);
            hl[k2] = __floats2half2_rn(v0 - __low2float(hh[k2]), v1 - __high2float(hh[k2]));
        }
        uint4 uh, ul;
        memcpy(&uh, hh, 16);
        memcpy(&ul, hl, 16);
        *reinterpret_cast<uint4*>(ch + base) = uh;
        *reinterpret_cast<uint4*>(cl + base) = ul;
        __syncwarp();
    }
}

static constexpr size_t FUSED_SMEM =
    ((size_t)128 * 72 + 2 * 128 * 72 + 2 * 128 * 72 + 128 * 136) * 2 +
    ((size_t)16 * 16 * 20 + 512 + 128) * 4;

// ---------------------------------------------------------------------------
// Head mean: out[b,q,k] = (1/16) sum_h expS[b,h,q,k] * invZ[b,h,q]
// ---------------------------------------------------------------------------
__global__ __launch_bounds__(256) void mean_h(const half* __restrict__ expsc,
                                              const float* __restrict__ invz,
                                              float* __restrict__ outw)
{
    const int q = blockIdx.x & (SS - 1);
    const int b = blockIdx.x >> 11;
    const int tid = threadIdx.x;

    float acc[8] = {0, 0, 0, 0, 0, 0, 0, 0};
#pragma unroll
    for (int h = 0; h < HH; h++) {
        const size_t off = (((size_t)(b * HH + h)) * SS + q) * SS;
        const float iz = __ldg(invz + (size_t)(b * HH + h) * SS + q);
        const uint4 u = reinterpret_cast<const uint4*>(expsc + off)[tid];
        __half2 h2[4];
        memcpy(h2, &u, 16);
#pragma unroll
        for (int k2 = 0; k2 < 4; k2++) {
            const float2 f = __half22float2(h2[k2]);
            acc[2 * k2]     += f.x * iz;
            acc[2 * k2 + 1] += f.y * iz;
        }
    }
    float* o = outw + ((size_t)b * SS + q) * SS + (size_t)tid * 8;
    *reinterpret_cast<float4*>(o)     = make_float4(acc[0] * (1.0f / HH), acc[1] * (1.0f / HH),
                                                    acc[2] * (1.0f / HH), acc[3] * (1.0f / HH));
    *reinterpret_cast<float4*>(o + 4) = make_float4(acc[4] * (1.0f / HH), acc[5] * (1.0f / HH),
                                                    acc[6] * (1.0f / HH), acc[7] * (1.0f / HH));
}

// ---------------------------------------------------------------------------
extern "C" void kernel_launch(void* const* d_in, const int* in_sizes, int n_in,
                              void* d_out, int out_size)
{
    const float* act[3] = {nullptr, nullptr, nullptr};
    const float* wgt[4] = {nullptr, nullptr, nullptr, nullptr};
    const float* bia[4] = {nullptr, nullptr, nullptr, nullptr};
    int na = 0, nw = 0, nb = 0;
    for (int i = 0; i < n_in; i++) {
        const int sz = in_sizes[i];
        if (sz == (int)NACT)      { if (na < 3) act[na++] = (const float*)d_in[i]; }
        else if (sz == (int)NW)   { if (nw < 4) wgt[nw++] = (const float*)d_in[i]; }
        else if (sz == DD)        { if (nb < 4) bia[nb++] = (const float*)d_in[i]; }
    }
    const float* query = act[0];
    const float* key   = act[1];
    const float* value = act[2];
    const float *bq = bia[0], *bk = bia[1], *bv = bia[2], *bo = bia[3];

    float* out_proj = (float*)d_out;
    float* out_attn = (float*)d_out + NACT;

    half *qh, *kh, *vh, *Wqh, *Wkh, *Wvh, *Woh, *Wol;
    half *yqh, *ykh, *yvh, *ch, *cl, *es;
    float *iz;
    cudaGetSymbolAddress((void**)&qh, g_qh);
    cudaGetSymbolAddress((void**)&kh, g_kh);
    cudaGetSymbolAddress((void**)&vh, g_vh);
    cudaGetSymbolAddress((void**)&Wqh, g_Wqh);
    cudaGetSymbolAddress((void**)&Wkh, g_Wkh);
    cudaGetSymbolAddress((void**)&Wvh, g_Wvh);
    cudaGetSymbolAddress((void**)&Woh, g_Woh);
    cudaGetSymbolAddress((void**)&Wol, g_Wol);
    cudaGetSymbolAddress((void**)&yqh, g_yqh);
    cudaGetSymbolAddress((void**)&ykh, g_ykh);
    cudaGetSymbolAddress((void**)&yvh, g_yvh);
    cudaGetSymbolAddress((void**)&ch, g_ch);
    cudaGetSymbolAddress((void**)&cl, g_cl);
    cudaGetSymbolAddress((void**)&es, g_es);
    cudaGetSymbolAddress((void**)&iz, g_iz);

    cudaFuncSetAttribute(proj_h, cudaFuncAttributeMaxDynamicSharedMemorySize, (int)SM_PROJ);
    cudaFuncSetAttribute(gemm_out, cudaFuncAttributeMaxDynamicSharedMemorySize, (int)SM_OUT);
    cudaFuncSetAttribute(fused_attn, cudaFuncAttributeMaxDynamicSharedMemorySize, (int)FUSED_SMEM);

    // 0: converts (q,k,v and Wq,Wk,Wv hi-only) + Wo split
    {
        const int n1 = (int)(NACT / 4), n2 = (int)(NW / 4);
        dim3 g1((n1 + 255) / 256, 3);
        conv3_v4<<<g1, 256>>>((const float4*)query, (const float4*)key, (const float4*)value,
                              (uint2*)qh, (uint2*)kh, (uint2*)vh, n1);
        dim3 g2((n2 + 255) / 256, 3);
        conv3_v4<<<g2, 256>>>((const float4*)wgt[0], (const float4*)wgt[1], (const float4*)wgt[2],
                              (uint2*)Wqh, (uint2*)Wkh, (uint2*)Wvh, n2);
        split_f32_v4<<<(n2 + 255) / 256, 256>>>((const float4*)wgt[3], (uint2*)Woh, (uint2*)Wol, n2);
    }

    // 1: all three projections in one launch (pure fp16)
    {
        dim3 gp(DD / 128, (BB * SS) / 128, 3);
        proj_h<<<gp, 256, SM_PROJ>>>(qh, kh, vh, Wqh, Wkh, Wvh, bq, bk, bv, yqh, ykh, yvh);
    }

    // 2: fused attention (QK^T -> exp -> PV), 512 threads
    {
        dim3 ga(SS / 128, BB * HH, 1);
        fused_attn<<<ga, 512, FUSED_SMEM>>>(yqh, ykh, yvh, es, iz, ch, cl);
    }

    // 3: head-mean of attention weights
    mean_h<<<BB * SS, 256>>>(es, iz, out_attn);

    // 4: out = ctx @ Wo^T + bo (full split)
    {
        dim3 gp(DD / 128, (BB * SS) / 128, 1);
        gemm_out<<<gp, 256, SM_OUT>>>(ch, cl, Woh, Wol, bo, out_proj);
    }
}

// round 16
// speedup vs baseline: 1.0518x; 1.0518x over previous
#include <cuda_runtime.h>
#include <cuda_fp16.h>
#include <mma.h>
#include <cstddef>
#include <cstdint>
#include <type_traits>

using namespace nvcuda;

#define BB 2
#define SS 2048
#define DD 1024
#define HH 16
#define DKK 64

#define NACT ((size_t)BB * SS * DD)     // 4,194,304
#define NW   ((size_t)DD * DD)          // 1,048,576

// ---- scratch (device globals) ----
__device__ half g_qh[NACT], g_kh[NACT], g_vh[NACT];
__device__ half g_Wqh[NW], g_Wkh[NW], g_Wvh[NW];
__device__ half g_Woh[NW], g_Wol[NW];
__device__ half g_yqh[NACT], g_ykh[NACT], g_yvh[NACT];
__device__ half g_ch[NACT], g_cl[NACT];
__device__ half g_es[(size_t)BB * HH * SS * SS];       // un-normalized exp(scores), fp16
__device__ float g_iz[(size_t)BB * HH * SS];           // 1/Z per row

// ---------------------------------------------------------------------------
__device__ __forceinline__ void cp_async16(void* smem_dst, const void* gmem_src) {
    uint32_t s = (uint32_t)__cvta_generic_to_shared(smem_dst);
    asm volatile("cp.async.cg.shared.global [%0], [%1], 16;" :: "r"(s), "l"(gmem_src) : "memory");
}
__device__ __forceinline__ void cp_commit() {
    asm volatile("cp.async.commit_group;" ::: "memory");
}
__device__ __forceinline__ void cp_wait1() {
    asm volatile("cp.async.wait_group 1;" ::: "memory");
}
__device__ __forceinline__ void cp_wait0() {
    asm volatile("cp.async.wait_group 0;" ::: "memory");
}

// ---------------------------------------------------------------------------
// fp32 -> fp16 convert (hi only), 3 tensors batched via blockIdx.y
// ---------------------------------------------------------------------------
__global__ void conv3_v4(const float4* __restrict__ x0, const float4* __restrict__ x1,
                         const float4* __restrict__ x2,
                         uint2* __restrict__ y0, uint2* __restrict__ y1,
                         uint2* __restrict__ y2, int n4)
{
    const int z = blockIdx.y;
    const float4* x = (z == 0) ? x0 : (z == 1) ? x1 : x2;
    uint2* y = (z == 0) ? y0 : (z == 1) ? y1 : y2;
    int i = blockIdx.x * blockDim.x + threadIdx.x;
    if (i < n4) {
        const float4 v = x[i];
        __half2 h01 = __floats2half2_rn(v.x, v.y);
        __half2 h23 = __floats2half2_rn(v.z, v.w);
        uint2 u; memcpy(&u, &h01, 4); memcpy(((char*)&u) + 4, &h23, 4);
        y[i] = u;
    }
}

// fp32 -> (hi, lo) split (Wo only)
__global__ void split_f32_v4(const float4* __restrict__ x, uint2* __restrict__ hi,
                             uint2* __restrict__ lo, int n4)
{
    int i = blockIdx.x * blockDim.x + threadIdx.x;
    if (i < n4) {
        const float4 v = x[i];
        __half2 h01 = __floats2half2_rn(v.x, v.y);
        __half2 h23 = __floats2half2_rn(v.z, v.w);
        uint2 uh; memcpy(&uh, &h01, 4); memcpy(((char*)&uh) + 4, &h23, 4);
        hi[i] = uh;
        __half2 l01 = __floats2half2_rn(v.x - __low2float(h01), v.y - __high2float(h01));
        __half2 l23 = __floats2half2_rn(v.z - __low2float(h23), v.w - __high2float(h23));
        uint2 ul; memcpy(&ul, &l01, 4); memcpy(((char*)&ul) + 4, &l23, 4);
        lo[i] = ul;
    }
}

// ---------------------------------------------------------------------------
// Pure-fp16 projection GEMM, 3 projections batched via blockIdx.z.
// B-fragments hoisted out of the i-loop (loaded once per ks).
// ---------------------------------------------------------------------------
__global__ __launch_bounds__(256) void proj_h(
    const half* __restrict__ A0, const half* __restrict__ A1, const half* __restrict__ A2,
    const half* __restrict__ B0, const half* __restrict__ B1, const half* __restrict__ B2,
    const float* __restrict__ b0, const float* __restrict__ b1, const float* __restrict__ b2,
    half* __restrict__ C0, half* __restrict__ C1, half* __restrict__ C2)
{
    constexpr int BM = 128, BN = 128, BK = 32;
    constexpr int LDA = BK + 8;
    constexpr int ASZ = BM * LDA;
    constexpr int BSZ = BN * LDA;
    constexpr int LDST = 20;

    extern __shared__ __align__(16) char smem_raw[];
    half* Ash = (half*)smem_raw;
    half* Bsh = Ash + 2 * ASZ;
    float* stage = (float*)(Bsh + 2 * BSZ);

    const int z = blockIdx.z;
    const half* A = (z == 0) ? A0 : (z == 1) ? A1 : A2;
    const half* B = (z == 0) ? B0 : (z == 1) ? B1 : B2;
    const float* bias = (z == 0) ? b0 : (z == 1) ? b1 : b2;
    half* C = (z == 0) ? C0 : (z == 1) ? C1 : C2;

    const int tm = blockIdx.y * BM;
    const int tn = blockIdx.x * BN;
    const int tid = threadIdx.x;
    const int wid = tid >> 5, lane = tid & 31;
    const int wm0 = (wid >> 1) * 32;
    const int wn0 = (wid & 1) * 64;

    auto load_stage = [&](int st, int k0) {
        half* ah = Ash + st * ASZ;
        half* bh = Bsh + st * BSZ;
#pragma unroll
        for (int i = tid; i < BM * (BK / 8); i += 256) {
            const int r = i >> 2, q = i & 3;
            cp_async16(&ah[r * LDA + q * 8], A + (size_t)(tm + r) * DD + k0 + q * 8);
            cp_async16(&bh[r * LDA + q * 8], B + (size_t)(tn + r) * DD + k0 + q * 8);
        }
    };

    wmma::fragment<wmma::matrix_a, 16, 16, 16, half, wmma::row_major> fa;
    wmma::fragment<wmma::matrix_b, 16, 16, 16, half, wmma::col_major> fb[4];
    wmma::fragment<wmma::accumulator, 16, 16, 16, float> acc[2][4];

#pragma unroll
    for (int i = 0; i < 2; i++)
#pragma unroll
        for (int j = 0; j < 4; j++) wmma::fill_fragment(acc[i][j], 0.0f);

    const int nIter = DD / BK;
    load_stage(0, 0);
    cp_commit();

    for (int it = 0; it < nIter; it++) {
        if (it + 1 < nIter) {
            load_stage((it + 1) & 1, (it + 1) * BK);
            cp_commit();
            cp_wait1();
        } else {
            cp_wait0();
        }
        __syncthreads();

        const half* ah = Ash + (it & 1) * ASZ;
        const half* bh = Bsh + (it & 1) * BSZ;

#pragma unroll
        for (int ks = 0; ks < 2; ks++) {
#pragma unroll
            for (int j = 0; j < 4; j++)
                wmma::load_matrix_sync(fb[j], &bh[(wn0 + j * 16) * LDA + ks * 16], LDA);
#pragma unroll
            for (int i = 0; i < 2; i++) {
                wmma::load_matrix_sync(fa, &ah[(wm0 + i * 16) * LDA + ks * 16], LDA);
#pragma unroll
                for (int j = 0; j < 4; j++)
                    wmma::mma_sync(acc[i][j], fa, fb[j], acc[i][j]);
            }
        }
        __syncthreads();
    }

    float* st = stage + wid * 16 * LDST;
#pragma unroll
    for (int i = 0; i < 2; i++)
#pragma unroll
        for (int j = 0; j < 4; j++) {
            wmma::store_matrix_sync(st, acc[i][j], LDST, wmma::mem_row_major);
            __syncwarp();
            const int r  = lane >> 1;
            const int c0 = (lane & 1) * 8;
            const int gn = tn + wn0 + j * 16 + c0;
            const size_t base = (size_t)(tm + wm0 + i * 16 + r) * DD + gn;
            __half2 hp[4];
#pragma unroll
            for (int k2 = 0; k2 < 4; k2++)
                hp[k2] = __floats2half2_rn(st[r * LDST + c0 + 2 * k2]     + bias[gn + 2 * k2],
                                           st[r * LDST + c0 + 2 * k2 + 1] + bias[gn + 2 * k2 + 1]);
            uint4 u;
            memcpy(&u, hp, 16);
            *reinterpret_cast<uint4*>(C + base) = u;
            __syncwarp();
        }
}
static constexpr size_t SM_PROJ = (size_t)(2 * 128 * 40 + 2 * 128 * 40) * 2 + 8 * 16 * 20 * 4;

// ---------------------------------------------------------------------------
// Output projection: out = (ch+cl) @ (Woh+Wol)^T + bo, fp32 out (3-mma split).
// B-fragments hoisted out of the i-loop.
// ---------------------------------------------------------------------------
__global__ __launch_bounds__(256) void gemm_out(
    const half* __restrict__ Ahi, const half* __restrict__ Alo,
    const half* __restrict__ Bhi, const half* __restrict__ Blo,
    const float* __restrict__ bias, float* __restrict__ Cf)
{
    constexpr int BM = 128, BN = 128, BK = 32;
    constexpr int LDA = BK + 8;
    constexpr int ASZ = BM * LDA;
    constexpr int BSZ = BN * LDA;
    constexpr int LDST = 20;

    extern __shared__ __align__(16) char smem_raw[];
    half* p = (half*)smem_raw;
    half* Ash = p;  p += 2 * ASZ;
    half* Asl = p;  p += 2 * ASZ;
    half* Bsh = p;  p += 2 * BSZ;
    half* Bsl = p;  p += 2 * BSZ;
    float* stage = (float*)p;

    const int tm = blockIdx.y * BM;
    const int tn = blockIdx.x * BN;
    const int tid = threadIdx.x;
    const int wid = tid >> 5, lane = tid & 31;
    const int wm0 = (wid >> 1) * 32;
    const int wn0 = (wid & 1) * 64;

    auto load_stage = [&](int st, int k0) {
#pragma unroll
        for (int i = tid; i < BM * (BK / 8); i += 256) {
            const int r = i >> 2, q = i & 3;
            cp_async16(&Ash[st * ASZ + r * LDA + q * 8], Ahi + (size_t)(tm + r) * DD + k0 + q * 8);
            cp_async16(&Asl[st * ASZ + r * LDA + q * 8], Alo + (size_t)(tm + r) * DD + k0 + q * 8);
            cp_async16(&Bsh[st * BSZ + r * LDA + q * 8], Bhi + (size_t)(tn + r) * DD + k0 + q * 8);
            cp_async16(&Bsl[st * BSZ + r * LDA + q * 8], Blo + (size_t)(tn + r) * DD + k0 + q * 8);
        }
    };

    wmma::fragment<wmma::matrix_a, 16, 16, 16, half, wmma::row_major> fa, fal;
    wmma::fragment<wmma::matrix_b, 16, 16, 16, half, wmma::col_major> fb[4], fbl[4];
    wmma::fragment<wmma::accumulator, 16, 16, 16, float> acc[2][4];

#pragma unroll
    for (int i = 0; i < 2; i++)
#pragma unroll
        for (int j = 0; j < 4; j++) wmma::fill_fragment(acc[i][j], 0.0f);

    const int nIter = DD / BK;
    load_stage(0, 0);
    cp_commit();

    for (int it = 0; it < nIter; it++) {
        if (it + 1 < nIter) {
            load_stage((it + 1) & 1, (it + 1) * BK);
            cp_commit();
            cp_wait1();
        } else {
            cp_wait0();
        }
        __syncthreads();

        const half* ah = Ash + (it & 1) * ASZ;
        const half* al = Asl + (it & 1) * ASZ;
        const half* bh = Bsh + (it & 1) * BSZ;
        const half* bl = Bsl + (it & 1) * BSZ;

#pragma unroll
        for (int ks = 0; ks < 2; ks++) {
#pragma unroll
            for (int j = 0; j < 4; j++) {
                wmma::load_matrix_sync(fb[j],  &bh[(wn0 + j * 16) * LDA + ks * 16], LDA);
                wmma::load_matrix_sync(fbl[j], &bl[(wn0 + j * 16) * LDA + ks * 16], LDA);
            }
#pragma unroll
            for (int i = 0; i < 2; i++) {
                wmma::load_matrix_sync(fa,  &ah[(wm0 + i * 16) * LDA + ks * 16], LDA);
                wmma::load_matrix_sync(fal, &al[(wm0 + i * 16) * LDA + ks * 16], LDA);
#pragma unroll
                for (int j = 0; j < 4; j++) {
                    wmma::mma_sync(acc[i][j], fa, fb[j], acc[i][j]);
                    wmma::mma_sync(acc[i][j], fal, fb[j], acc[i][j]);
                    wmma::mma_sync(acc[i][j], fa, fbl[j], acc[i][j]);
                }
            }
        }
        __syncthreads();
    }

    float* st = stage + wid * 16 * LDST;
#pragma unroll
    for (int i = 0; i < 2; i++)
#pragma unroll
        for (int j = 0; j < 4; j++) {
            wmma::store_matrix_sync(st, acc[i][j], LDST, wmma::mem_row_major);
            __syncwarp();
            const int r  = lane >> 1;
            const int c0 = (lane & 1) * 8;
            const int gn = tn + wn0 + j * 16 + c0;
            const size_t base = (size_t)(tm + wm0 + i * 16 + r) * DD + gn;
            float v[8];
#pragma unroll
            for (int e = 0; e < 8; e++) v[e] = st[r * LDST + c0 + e] + bias[gn + e];
            *reinterpret_cast<float4*>(Cf + base)     = make_float4(v[0], v[1], v[2], v[3]);
            *reinterpret_cast<float4*>(Cf + base + 4) = make_float4(v[4], v[5], v[6], v[7]);
            __syncwarp();
        }
}
static constexpr size_t SM_OUT = (size_t)(4 * 128 * 40 + 4 * 128 * 40) * 2 + 8 * 16 * 20 * 4;

// ---------------------------------------------------------------------------
// Fused attention, 256 threads (reverted from 512 — regression), with hoisted
// B-fragment loads. Per block = (q-tile 128, b*h).
// ---------------------------------------------------------------------------
__global__ __launch_bounds__(256) void fused_attn(
    const half* __restrict__ yq, const half* __restrict__ yk,
    const half* __restrict__ yv,
    half* __restrict__ expsc, float* __restrict__ invz,
    half* __restrict__ ch, half* __restrict__ cl)
{
    constexpr int LDQ = 72;
    constexpr int LDS = 136;
    constexpr int QSZ = 128 * LDQ;
    constexpr int KSZ = 128 * LDQ;

    extern __shared__ __align__(16) char smem_raw[];
    half* Qs  = (half*)smem_raw;
    half* Ks  = Qs + QSZ;
    half* Vs  = Ks + 2 * KSZ;
    half* S16 = Vs + 2 * KSZ;
    float* stage = (float*)(S16 + 128 * LDS);
    float* psum  = stage + 8 * 16 * 20;
    float* Zs    = psum + 256;

    const int qt = blockIdx.x;
    const int bh = blockIdx.y;
    const int b  = bh >> 4, h = bh & 15;
    const int q0 = qt * 128;

    const half* Qg = yq + ((size_t)b * SS + q0) * DD + h * DKK;
    const half* Kg = yk + (size_t)b * SS * DD + h * DKK;
    const half* Vg = yv + (size_t)b * SS * DD + h * DKK;
    half* Erow = expsc + ((size_t)bh * SS + q0) * SS;

    const int tid = threadIdx.x;
    const int wid = tid >> 5, lane = tid & 31;
    const int wm0 = (wid >> 1) * 32;
    const int wn0 = (wid & 1) * 64;
    const int wnU = (wid & 1) * 32;

    if (tid < 128) Zs[tid] = 0.0f;

    auto load_kv = [&](int st, int kt) {
#pragma unroll
        for (int i = tid; i < 1024; i += 256) {
            const int r = i >> 3, c = i & 7;
            cp_async16(&Ks[st * KSZ + r * LDQ + c * 8],
                       Kg + (size_t)(kt * 128 + r) * DD + c * 8);
            cp_async16(&Vs[st * KSZ + r * LDQ + c * 8],
                       Vg + (size_t)(kt * 128 + r) * DD + c * 8);
        }
    };

#pragma unroll
    for (int i = tid; i < 1024; i += 256) {
        const int r = i >> 3, c = i & 7;
        cp_async16(&Qs[r * LDQ + c * 8], Qg + (size_t)r * DD + c * 8);
    }
    load_kv(0, 0);
    cp_commit();

    wmma::fragment<wmma::matrix_a, 16, 16, 16, half, wmma::row_major> fa;
    wmma::fragment<wmma::matrix_b, 16, 16, 16, half, wmma::col_major> fbT[4];
    wmma::fragment<wmma::matrix_b, 16, 16, 16, half, wmma::row_major> fbN[2];
    wmma::fragment<wmma::accumulator, 16, 16, 16, float> sacc[2][4];
    wmma::fragment<wmma::accumulator, 16, 16, 16, float> uacc[2][2];

#pragma unroll
    for (int i = 0; i < 2; i++)
#pragma unroll
        for (int j = 0; j < 2; j++) wmma::fill_fragment(uacc[i][j], 0.0f);

    float* st = stage + wid * 16 * 20;

    for (int kt = 0; kt < SS / 128; kt++) {
        if (kt + 1 < SS / 128) {
            load_kv((kt + 1) & 1, kt + 1);
            cp_commit();
            cp_wait1();
        } else {
            cp_wait0();
        }
        __syncthreads();

        const half* Kst = Ks + (kt & 1) * KSZ;
        const half* Vst = Vs + (kt & 1) * KSZ;

        // ---- S = Q @ K^T (128x128, K=64), B-fragments hoisted ----
#pragma unroll
        for (int i = 0; i < 2; i++)
#pragma unroll
            for (int j = 0; j < 4; j++) wmma::fill_fragment(sacc[i][j], 0.0f);
#pragma unroll
        for (int kf = 0; kf < 4; kf++) {
#pragma unroll
            for (int j = 0; j < 4; j++)
                wmma::load_matrix_sync(fbT[j], &Kst[(wn0 + j * 16) * LDQ + kf * 16], LDQ);
#pragma unroll
            for (int i = 0; i < 2; i++) {
                wmma::load_matrix_sync(fa, &Qs[(wm0 + i * 16) * LDQ + kf * 16], LDQ);
#pragma unroll
                for (int j = 0; j < 4; j++)
                    wmma::mma_sync(sacc[i][j], fa, fbT[j], sacc[i][j]);
            }
        }

        // ---- exp + fp16 tile in smem ----
#pragma unroll
        for (int i = 0; i < 2; i++)
#pragma unroll
            for (int j = 0; j < 4; j++) {
#pragma unroll
                for (int e = 0; e < 8; e++)
                    sacc[i][j].x[e] = __expf(sacc[i][j].x[e] * 0.125f);
                wmma::store_matrix_sync(st, sacc[i][j], 20, wmma::mem_row_major);
                __syncwarp();
                const int r  = lane >> 1;
                const int c0 = (lane & 1) * 8;
                __half2 hp[4];
#pragma unroll
                for (int k2 = 0; k2 < 4; k2++)
                    hp[k2] = __floats2half2_rn(st[r * 20 + c0 + 2 * k2],
                                               st[r * 20 + c0 + 2 * k2 + 1]);
                uint4 u;
                memcpy(&u, hp, 16);
                *reinterpret_cast<uint4*>(&S16[(wm0 + i * 16 + r) * LDS + wn0 + j * 16 + c0]) = u;
                __syncwarp();
            }
        __syncthreads();

        // ---- Z partials + gmem copy of expS tile ----
        {
            const int r = tid >> 1, hf = tid & 1;
            const __half2* p2 = reinterpret_cast<const __half2*>(&S16[r * LDS + hf * 64]);
            float s = 0.0f;
#pragma unroll
            for (int i = 0; i < 32; i++) {
                const float2 f = __half22float2(p2[i]);
                s += f.x + f.y;
            }
            psum[tid] = s;
        }
#pragma unroll
        for (int idx = tid; idx < 2048; idx += 256) {
            const int r = idx >> 4, c = idx & 15;
            *reinterpret_cast<uint4*>(Erow + (size_t)r * SS + kt * 128 + c * 8) =
                *reinterpret_cast<const uint4*>(&S16[r * LDS + c * 8]);
        }
        __syncthreads();
        if (tid < 128) Zs[tid] += psum[2 * tid] + psum[2 * tid + 1];

        // ---- U += expS @ V (128x64, K=128), B-fragments hoisted ----
#pragma unroll
        for (int kf = 0; kf < 8; kf++) {
#pragma unroll
            for (int j = 0; j < 2; j++)
                wmma::load_matrix_sync(fbN[j], &Vst[(kf * 16) * LDQ + wnU + j * 16], LDQ);
#pragma unroll
            for (int i = 0; i < 2; i++) {
                wmma::load_matrix_sync(fa, &S16[(wm0 + i * 16) * LDS + kf * 16], LDS);
#pragma unroll
                for (int j = 0; j < 2; j++)
                    wmma::mma_sync(uacc[i][j], fa, fbN[j], uacc[i][j]);
            }
        }
        __syncthreads();
    }

    if (tid < 128) {
        const float iz = 1.0f / Zs[tid];
        Zs[tid] = iz;
        invz[(size_t)bh * SS + q0 + tid] = iz;
    }
    __syncthreads();

#pragma unroll
    for (int i = 0; i < 2; i++)
#pragma unroll
        for (int j = 0; j < 2; j++) {
            wmma::store_matrix_sync(st, uacc[i][j], 20, wmma::mem_row_major);
            __syncwarp();
            const int r  = lane >> 1;
            const int c0 = (lane & 1) * 8;
            const int row = wm0 + i * 16 + r;
            const float iz = Zs[row];
            const size_t base = ((size_t)b * SS + q0 + row) * DD + h * DKK + wnU + j * 16 + c0;
            __half2 hh[4], hl[4];
#pragma unroll
            for (int k2 = 0; k2 < 4; k2++) {
                const float v0 = st[r * 20 + c0 + 2 * k2] * iz;
                const float v1 = st[r * 20 + c0 + 2 * k2 + 1] * iz;
                hh[k2] = __floats2half2_rn(v0, v1);
                hl[k2] = __floats2half2_rn(v0 - __low2float(hh[k2]), v1 - __high2float(hh[k2]));
            }
            uint4 uh, ul;
            memcpy(&uh, hh, 16);
            memcpy(&ul, hl, 16);
            *reinterpret_cast<uint4*>(ch + base) = uh;
            *reinterpret_cast<uint4*>(cl + base) = ul;
            __syncwarp();
        }
}

static constexpr size_t FUSED_SMEM =
    ((size_t)128 * 72 + 2 * 128 * 72 + 2 * 128 * 72 + 128 * 136) * 2 +
    ((size_t)8 * 16 * 20 + 256 + 128) * 4;

// ---------------------------------------------------------------------------
// Head mean: out[b,q,k] = (1/16) sum_h expS[b,h,q,k] * invZ[b,h,q]
// ---------------------------------------------------------------------------
__global__ __launch_bounds__(256) void mean_h(const half* __restrict__ expsc,
                                              const float* __restrict__ invz,
                                              float* __restrict__ outw)
{
    const int q = blockIdx.x & (SS - 1);
    const int b = blockIdx.x >> 11;
    const int tid = threadIdx.x;

    float acc[8] = {0, 0, 0, 0, 0, 0, 0, 0};
#pragma unroll
    for (int h = 0; h < HH; h++) {
        const size_t off = (((size_t)(b * HH + h)) * SS + q) * SS;
        const float iz = __ldg(invz + (size_t)(b * HH + h) * SS + q);
        const uint4 u = reinterpret_cast<const uint4*>(expsc + off)[tid];
        __half2 h2[4];
        memcpy(h2, &u, 16);
#pragma unroll
        for (int k2 = 0; k2 < 4; k2++) {
            const float2 f = __half22float2(h2[k2]);
            acc[2 * k2]     += f.x * iz;
            acc[2 * k2 + 1] += f.y * iz;
        }
    }
    float* o = outw + ((size_t)b * SS + q) * SS + (size_t)tid * 8;
    *reinterpret_cast<float4*>(o)     = make_float4(acc[0] * (1.0f / HH), acc[1] * (1.0f / HH),
                                                    acc[2] * (1.0f / HH), acc[3] * (1.0f / HH));
    *reinterpret_cast<float4*>(o + 4) = make_float4(acc[4] * (1.0f / HH), acc[5] * (1.0f / HH),
                                                    acc[6] * (1.0f / HH), acc[7] * (1.0f / HH));
}

// ---------------------------------------------------------------------------
extern "C" void kernel_launch(void* const* d_in, const int* in_sizes, int n_in,
                              void* d_out, int out_size)
{
    const float* act[3] = {nullptr, nullptr, nullptr};
    const float* wgt[4] = {nullptr, nullptr, nullptr, nullptr};
    const float* bia[4] = {nullptr, nullptr, nullptr, nullptr};
    int na = 0, nw = 0, nb = 0;
    for (int i = 0; i < n_in; i++) {
        const int sz = in_sizes[i];
        if (sz == (int)NACT)      { if (na < 3) act[na++] = (const float*)d_in[i]; }
        else if (sz == (int)NW)   { if (nw < 4) wgt[nw++] = (const float*)d_in[i]; }
        else if (sz == DD)        { if (nb < 4) bia[nb++] = (const float*)d_in[i]; }
    }
    const float* query = act[0];
    const float* key   = act[1];
    const float* value = act[2];
    const float *bq = bia[0], *bk = bia[1], *bv = bia[2], *bo = bia[3];

    float* out_proj = (float*)d_out;
    float* out_attn = (float*)d_out + NACT;

    half *qh, *kh, *vh, *Wqh, *Wkh, *Wvh, *Woh, *Wol;
    half *yqh, *ykh, *yvh, *ch, *cl, *es;
    float *iz;
    cudaGetSymbolAddress((void**)&qh, g_qh);
    cudaGetSymbolAddress((void**)&kh, g_kh);
    cudaGetSymbolAddress((void**)&vh, g_vh);
    cudaGetSymbolAddress((void**)&Wqh, g_Wqh);
    cudaGetSymbolAddress((void**)&Wkh, g_Wkh);
    cudaGetSymbolAddress((void**)&Wvh, g_Wvh);
    cudaGetSymbolAddress((void**)&Woh, g_Woh);
    cudaGetSymbolAddress((void**)&Wol, g_Wol);
    cudaGetSymbolAddress((void**)&yqh, g_yqh);
    cudaGetSymbolAddress((void**)&ykh, g_ykh);
    cudaGetSymbolAddress((void**)&yvh, g_yvh);
    cudaGetSymbolAddress((void**)&ch, g_ch);
    cudaGetSymbolAddress((void**)&cl, g_cl);
    cudaGetSymbolAddress((void**)&es, g_es);
    cudaGetSymbolAddress((void**)&iz, g_iz);

    cudaFuncSetAttribute(proj_h, cudaFuncAttributeMaxDynamicSharedMemorySize, (int)SM_PROJ);
    cudaFuncSetAttribute(gemm_out, cudaFuncAttributeMaxDynamicSharedMemorySize, (int)SM_OUT);
    cudaFuncSetAttribute(fused_attn, cudaFuncAttributeMaxDynamicSharedMemorySize, (int)FUSED_SMEM);

    // 0: converts (q,k,v and Wq,Wk,Wv hi-only) + Wo split
    {
        const int n1 = (int)(NACT / 4), n2 = (int)(NW / 4);
        dim3 g1((n1 + 255) / 256, 3);
        conv3_v4<<<g1, 256>>>((const float4*)query, (const float4*)key, (const float4*)value,
                              (uint2*)qh, (uint2*)kh, (uint2*)vh, n1);
        dim3 g2((n2 + 255) / 256, 3);
        conv3_v4<<<g2, 256>>>((const float4*)wgt[0], (const float4*)wgt[1], (const float4*)wgt[2],
                              (uint2*)Wqh, (uint2*)Wkh, (uint2*)Wvh, n2);
        split_f32_v4<<<(n2 + 255) / 256, 256>>>((const float4*)wgt[3], (uint2*)Woh, (uint2*)Wol, n2);
    }

    // 1: all three projections in one launch (pure fp16)
    {
        dim3 gp(DD / 128, (BB * SS) / 128, 3);
        proj_h<<<gp, 256, SM_PROJ>>>(qh, kh, vh, Wqh, Wkh, Wvh, bq, bk, bv, yqh, ykh, yvh);
    }

    // 2: fused attention (QK^T -> exp -> PV), 256 threads
    {
        dim3 ga(SS / 128, BB * HH, 1);
        fused_attn<<<ga, 256, FUSED_SMEM>>>(yqh, ykh, yvh, es, iz, ch, cl);
    }

    // 3: head-mean of attention weights
    mean_h<<<BB * SS, 256>>>(es, iz, out_attn);

    // 4: out = ctx @ Wo^T + bo (full split)
    {
        dim3 gp(DD / 128, (BB * SS) / 128, 1);
        gemm_out<<<gp, 256, SM_OUT>>>(ch, cl, Woh, Wol, bo, out_proj);
    }
}

// round 17
// speedup vs baseline: 1.1001x; 1.0460x over previous
#include <cuda_runtime.h>
#include <cuda_fp16.h>
#include <mma.h>
#include <cstddef>
#include <cstdint>
#include <type_traits>

using namespace nvcuda;

#define BB 2
#define SS 2048
#define DD 1024
#define HH 16
#define DKK 64

#define NACT ((size_t)BB * SS * DD)     // 4,194,304
#define NW   ((size_t)DD * DD)          // 1,048,576

// ---- scratch (device globals) ----
__device__ half g_qh[NACT], g_kh[NACT], g_vh[NACT];
__device__ half g_Wqh[NW], g_Wkh[NW], g_Wvh[NW];
__device__ half g_Woh[NW], g_Wol[NW];
__device__ half g_yqh[NACT], g_ykh[NACT], g_yvh[NACT];
__device__ half g_ch[NACT];
__device__ half g_es[(size_t)BB * HH * SS * SS];       // un-normalized exp(scores), fp16
__device__ float g_iz[(size_t)BB * HH * SS];           // 1/Z per row

// ---------------------------------------------------------------------------
__device__ __forceinline__ void cp_async16(void* smem_dst, const void* gmem_src) {
    uint32_t s = (uint32_t)__cvta_generic_to_shared(smem_dst);
    asm volatile("cp.async.cg.shared.global [%0], [%1], 16;" :: "r"(s), "l"(gmem_src) : "memory");
}
__device__ __forceinline__ void cp_commit() {
    asm volatile("cp.async.commit_group;" ::: "memory");
}
__device__ __forceinline__ void cp_wait2() {
    asm volatile("cp.async.wait_group 2;" ::: "memory");
}
__device__ __forceinline__ void cp_wait1() {
    asm volatile("cp.async.wait_group 1;" ::: "memory");
}
__device__ __forceinline__ void cp_wait0() {
    asm volatile("cp.async.wait_group 0;" ::: "memory");
}

// ---------------------------------------------------------------------------
// fp32 -> fp16 convert (hi only), 3 tensors batched via blockIdx.y
// ---------------------------------------------------------------------------
__global__ void conv3_v4(const float4* __restrict__ x0, const float4* __restrict__ x1,
                         const float4* __restrict__ x2,
                         uint2* __restrict__ y0, uint2* __restrict__ y1,
                         uint2* __restrict__ y2, int n4)
{
    const int z = blockIdx.y;
    const float4* x = (z == 0) ? x0 : (z == 1) ? x1 : x2;
    uint2* y = (z == 0) ? y0 : (z == 1) ? y1 : y2;
    int i = blockIdx.x * blockDim.x + threadIdx.x;
    if (i < n4) {
        const float4 v = x[i];
        __half2 h01 = __floats2half2_rn(v.x, v.y);
        __half2 h23 = __floats2half2_rn(v.z, v.w);
        uint2 u; memcpy(&u, &h01, 4); memcpy(((char*)&u) + 4, &h23, 4);
        y[i] = u;
    }
}

// fp32 -> (hi, lo) split (Wo only)
__global__ void split_f32_v4(const float4* __restrict__ x, uint2* __restrict__ hi,
                             uint2* __restrict__ lo, int n4)
{
    int i = blockIdx.x * blockDim.x + threadIdx.x;
    if (i < n4) {
        const float4 v = x[i];
        __half2 h01 = __floats2half2_rn(v.x, v.y);
        __half2 h23 = __floats2half2_rn(v.z, v.w);
        uint2 uh; memcpy(&uh, &h01, 4); memcpy(((char*)&uh) + 4, &h23, 4);
        hi[i] = uh;
        __half2 l01 = __floats2half2_rn(v.x - __low2float(h01), v.y - __high2float(h01));
        __half2 l23 = __floats2half2_rn(v.z - __low2float(h23), v.w - __high2float(h23));
        uint2 ul; memcpy(&ul, &l01, 4); memcpy(((char*)&ul) + 4, &l23, 4);
        lo[i] = ul;
    }
}

// ---------------------------------------------------------------------------
// Pure-fp16 projection GEMM, 3 projections batched via blockIdx.z.
// 3-stage cp.async pipeline (2 loads in flight) + hoisted B-fragments.
// ---------------------------------------------------------------------------
__global__ __launch_bounds__(256) void proj_h(
    const half* __restrict__ A0, const half* __restrict__ A1, const half* __restrict__ A2,
    const half* __restrict__ B0, const half* __restrict__ B1, const half* __restrict__ B2,
    const float* __restrict__ b0, const float* __restrict__ b1, const float* __restrict__ b2,
    half* __restrict__ C0, half* __restrict__ C1, half* __restrict__ C2)
{
    constexpr int BM = 128, BN = 128, BK = 32;
    constexpr int LDA = BK + 8;
    constexpr int ASZ = BM * LDA;
    constexpr int BSZ = BN * LDA;
    constexpr int LDST = 20;
    constexpr int NSTG = 3;

    extern __shared__ __align__(16) char smem_raw[];
    half* Ash = (half*)smem_raw;
    half* Bsh = Ash + NSTG * ASZ;
    float* stage = (float*)(Bsh + NSTG * BSZ);

    const int z = blockIdx.z;
    const half* A = (z == 0) ? A0 : (z == 1) ? A1 : A2;
    const half* B = (z == 0) ? B0 : (z == 1) ? B1 : B2;
    const float* bias = (z == 0) ? b0 : (z == 1) ? b1 : b2;
    half* C = (z == 0) ? C0 : (z == 1) ? C1 : C2;

    const int tm = blockIdx.y * BM;
    const int tn = blockIdx.x * BN;
    const int tid = threadIdx.x;
    const int wid = tid >> 5, lane = tid & 31;
    const int wm0 = (wid >> 1) * 32;
    const int wn0 = (wid & 1) * 64;

    auto load_stage = [&](int st, int k0) {
        half* ah = Ash + st * ASZ;
        half* bh = Bsh + st * BSZ;
#pragma unroll
        for (int i = tid; i < BM * (BK / 8); i += 256) {
            const int r = i >> 2, q = i & 3;
            cp_async16(&ah[r * LDA + q * 8], A + (size_t)(tm + r) * DD + k0 + q * 8);
            cp_async16(&bh[r * LDA + q * 8], B + (size_t)(tn + r) * DD + k0 + q * 8);
        }
    };

    wmma::fragment<wmma::matrix_a, 16, 16, 16, half, wmma::row_major> fa;
    wmma::fragment<wmma::matrix_b, 16, 16, 16, half, wmma::col_major> fb[4];
    wmma::fragment<wmma::accumulator, 16, 16, 16, float> acc[2][4];

#pragma unroll
    for (int i = 0; i < 2; i++)
#pragma unroll
        for (int j = 0; j < 4; j++) wmma::fill_fragment(acc[i][j], 0.0f);

    const int nIter = DD / BK;    // 32
    load_stage(0, 0);
    cp_commit();
    load_stage(1, BK);
    cp_commit();

    for (int it = 0; it < nIter; it++) {
        if (it + 2 < nIter) {
            load_stage((it + 2) % NSTG, (it + 2) * BK);
            cp_commit();
            cp_wait2();
        } else if (it + 1 < nIter) {
            cp_wait1();
        } else {
            cp_wait0();
        }
        __syncthreads();

        const half* ah = Ash + (it % NSTG) * ASZ;
        const half* bh = Bsh + (it % NSTG) * BSZ;

#pragma unroll
        for (int ks = 0; ks < 2; ks++) {
#pragma unroll
            for (int j = 0; j < 4; j++)
                wmma::load_matrix_sync(fb[j], &bh[(wn0 + j * 16) * LDA + ks * 16], LDA);
#pragma unroll
            for (int i = 0; i < 2; i++) {
                wmma::load_matrix_sync(fa, &ah[(wm0 + i * 16) * LDA + ks * 16], LDA);
#pragma unroll
                for (int j = 0; j < 4; j++)
                    wmma::mma_sync(acc[i][j], fa, fb[j], acc[i][j]);
            }
        }
        __syncthreads();
    }

    float* st = stage + wid * 16 * LDST;
#pragma unroll
    for (int i = 0; i < 2; i++)
#pragma unroll
        for (int j = 0; j < 4; j++) {
            wmma::store_matrix_sync(st, acc[i][j], LDST, wmma::mem_row_major);
            __syncwarp();
            const int r  = lane >> 1;
            const int c0 = (lane & 1) * 8;
            const int gn = tn + wn0 + j * 16 + c0;
            const size_t base = (size_t)(tm + wm0 + i * 16 + r) * DD + gn;
            __half2 hp[4];
#pragma unroll
            for (int k2 = 0; k2 < 4; k2++)
                hp[k2] = __floats2half2_rn(st[r * LDST + c0 + 2 * k2]     + bias[gn + 2 * k2],
                                           st[r * LDST + c0 + 2 * k2 + 1] + bias[gn + 2 * k2 + 1]);
            uint4 u;
            memcpy(&u, hp, 16);
            *reinterpret_cast<uint4*>(C + base) = u;
            __syncwarp();
        }
}
static constexpr size_t SM_PROJ = (size_t)(3 * 128 * 40 + 3 * 128 * 40) * 2 + 8 * 16 * 20 * 4;

// ---------------------------------------------------------------------------
// Output projection: out = ch @ (Woh+Wol)^T + bo, fp32 out (2-mma: A hi-only).
// ---------------------------------------------------------------------------
__global__ __launch_bounds__(256) void gemm_out(
    const half* __restrict__ Ahi,
    const half* __restrict__ Bhi, const half* __restrict__ Blo,
    const float* __restrict__ bias, float* __restrict__ Cf)
{
    constexpr int BM = 128, BN = 128, BK = 32;
    constexpr int LDA = BK + 8;
    constexpr int ASZ = BM * LDA;
    constexpr int BSZ = BN * LDA;
    constexpr int LDST = 20;

    extern __shared__ __align__(16) char smem_raw[];
    half* p = (half*)smem_raw;
    half* Ash = p;  p += 2 * ASZ;
    half* Bsh = p;  p += 2 * BSZ;
    half* Bsl = p;  p += 2 * BSZ;
    float* stage = (float*)p;

    const int tm = blockIdx.y * BM;
    const int tn = blockIdx.x * BN;
    const int tid = threadIdx.x;
    const int wid = tid >> 5, lane = tid & 31;
    const int wm0 = (wid >> 1) * 32;
    const int wn0 = (wid & 1) * 64;

    auto load_stage = [&](int st, int k0) {
#pragma unroll
        for (int i = tid; i < BM * (BK / 8); i += 256) {
            const int r = i >> 2, q = i & 3;
            cp_async16(&Ash[st * ASZ + r * LDA + q * 8], Ahi + (size_t)(tm + r) * DD + k0 + q * 8);
            cp_async16(&Bsh[st * BSZ + r * LDA + q * 8], Bhi + (size_t)(tn + r) * DD + k0 + q * 8);
            cp_async16(&Bsl[st * BSZ + r * LDA + q * 8], Blo + (size_t)(tn + r) * DD + k0 + q * 8);
        }
    };

    wmma::fragment<wmma::matrix_a, 16, 16, 16, half, wmma::row_major> fa;
    wmma::fragment<wmma::matrix_b, 16, 16, 16, half, wmma::col_major> fb[4], fbl[4];
    wmma::fragment<wmma::accumulator, 16, 16, 16, float> acc[2][4];

#pragma unroll
    for (int i = 0; i < 2; i++)
#pragma unroll
        for (int j = 0; j < 4; j++) wmma::fill_fragment(acc[i][j], 0.0f);

    const int nIter = DD / BK;
    load_stage(0, 0);
    cp_commit();

    for (int it = 0; it < nIter; it++) {
        if (it + 1 < nIter) {
            load_stage((it + 1) & 1, (it + 1) * BK);
            cp_commit();
            cp_wait1();
        } else {
            cp_wait0();
        }
        __syncthreads();

        const half* ah = Ash + (it & 1) * ASZ;
        const half* bh = Bsh + (it & 1) * BSZ;
        const half* bl = Bsl + (it & 1) * BSZ;

#pragma unroll
        for (int ks = 0; ks < 2; ks++) {
#pragma unroll
            for (int j = 0; j < 4; j++) {
                wmma::load_matrix_sync(fb[j],  &bh[(wn0 + j * 16) * LDA + ks * 16], LDA);
                wmma::load_matrix_sync(fbl[j], &bl[(wn0 + j * 16) * LDA + ks * 16], LDA);
            }
#pragma unroll
            for (int i = 0; i < 2; i++) {
                wmma::load_matrix_sync(fa, &ah[(wm0 + i * 16) * LDA + ks * 16], LDA);
#pragma unroll
                for (int j = 0; j < 4; j++) {
                    wmma::mma_sync(acc[i][j], fa, fb[j], acc[i][j]);
                    wmma::mma_sync(acc[i][j], fa, fbl[j], acc[i][j]);
                }
            }
        }
        __syncthreads();
    }

    float* st = stage + wid * 16 * LDST;
#pragma unroll
    for (int i = 0; i < 2; i++)
#pragma unroll
        for (int j = 0; j < 4; j++) {
            wmma::store_matrix_sync(st, acc[i][j], LDST, wmma::mem_row_major);
            __syncwarp();
            const int r  = lane >> 1;
            const int c0 = (lane & 1) * 8;
            const int gn = tn + wn0 + j * 16 + c0;
            const size_t base = (size_t)(tm + wm0 + i * 16 + r) * DD + gn;
            float v[8];
#pragma unroll
            for (int e = 0; e < 8; e++) v[e] = st[r * LDST + c0 + e] + bias[gn + e];
            *reinterpret_cast<float4*>(Cf + base)     = make_float4(v[0], v[1], v[2], v[3]);
            *reinterpret_cast<float4*>(Cf + base + 4) = make_float4(v[4], v[5], v[6], v[7]);
            __syncwarp();
        }
}
static constexpr size_t SM_OUT = (size_t)(2 * 128 * 40 + 4 * 128 * 40) * 2 + 8 * 16 * 20 * 4;

// ---------------------------------------------------------------------------
// Fused attention, 256 threads, hoisted B-fragments, ctx hi-only output.
// ---------------------------------------------------------------------------
__global__ __launch_bounds__(256) void fused_attn(
    const half* __restrict__ yq, const half* __restrict__ yk,
    const half* __restrict__ yv,
    half* __restrict__ expsc, float* __restrict__ invz,
    half* __restrict__ ch)
{
    constexpr int LDQ = 72;
    constexpr int LDS = 136;
    constexpr int QSZ = 128 * LDQ;
    constexpr int KSZ = 128 * LDQ;

    extern __shared__ __align__(16) char smem_raw[];
    half* Qs  = (half*)smem_raw;
    half* Ks  = Qs + QSZ;
    half* Vs  = Ks + 2 * KSZ;
    half* S16 = Vs + 2 * KSZ;
    float* stage = (float*)(S16 + 128 * LDS);
    float* psum  = stage + 8 * 16 * 20;
    float* Zs    = psum + 256;

    const int qt = blockIdx.x;
    const int bh = blockIdx.y;
    const int b  = bh >> 4, h = bh & 15;
    const int q0 = qt * 128;

    const half* Qg = yq + ((size_t)b * SS + q0) * DD + h * DKK;
    const half* Kg = yk + (size_t)b * SS * DD + h * DKK;
    const half* Vg = yv + (size_t)b * SS * DD + h * DKK;
    half* Erow = expsc + ((size_t)bh * SS + q0) * SS;

    const int tid = threadIdx.x;
    const int wid = tid >> 5, lane = tid & 31;
    const int wm0 = (wid >> 1) * 32;
    const int wn0 = (wid & 1) * 64;
    const int wnU = (wid & 1) * 32;

    if (tid < 128) Zs[tid] = 0.0f;

    auto load_kv = [&](int st, int kt) {
#pragma unroll
        for (int i = tid; i < 1024; i += 256) {
            const int r = i >> 3, c = i & 7;
            cp_async16(&Ks[st * KSZ + r * LDQ + c * 8],
                       Kg + (size_t)(kt * 128 + r) * DD + c * 8);
            cp_async16(&Vs[st * KSZ + r * LDQ + c * 8],
                       Vg + (size_t)(kt * 128 + r) * DD + c * 8);
        }
    };

#pragma unroll
    for (int i = tid; i < 1024; i += 256) {
        const int r = i >> 3, c = i & 7;
        cp_async16(&Qs[r * LDQ + c * 8], Qg + (size_t)r * DD + c * 8);
    }
    load_kv(0, 0);
    cp_commit();

    wmma::fragment<wmma::matrix_a, 16, 16, 16, half, wmma::row_major> fa;
    wmma::fragment<wmma::matrix_b, 16, 16, 16, half, wmma::col_major> fbT[4];
    wmma::fragment<wmma::matrix_b, 16, 16, 16, half, wmma::row_major> fbN[2];
    wmma::fragment<wmma::accumulator, 16, 16, 16, float> sacc[2][4];
    wmma::fragment<wmma::accumulator, 16, 16, 16, float> uacc[2][2];

#pragma unroll
    for (int i = 0; i < 2; i++)
#pragma unroll
        for (int j = 0; j < 2; j++) wmma::fill_fragment(uacc[i][j], 0.0f);

    float* st = stage + wid * 16 * 20;

    for (int kt = 0; kt < SS / 128; kt++) {
        if (kt + 1 < SS / 128) {
            load_kv((kt + 1) & 1, kt + 1);
            cp_commit();
            cp_wait1();
        } else {
            cp_wait0();
        }
        __syncthreads();

        const half* Kst = Ks + (kt & 1) * KSZ;
        const half* Vst = Vs + (kt & 1) * KSZ;

        // ---- S = Q @ K^T (128x128, K=64) ----
#pragma unroll
        for (int i = 0; i < 2; i++)
#pragma unroll
            for (int j = 0; j < 4; j++) wmma::fill_fragment(sacc[i][j], 0.0f);
#pragma unroll
        for (int kf = 0; kf < 4; kf++) {
#pragma unroll
            for (int j = 0; j < 4; j++)
                wmma::load_matrix_sync(fbT[j], &Kst[(wn0 + j * 16) * LDQ + kf * 16], LDQ);
#pragma unroll
            for (int i = 0; i < 2; i++) {
                wmma::load_matrix_sync(fa, &Qs[(wm0 + i * 16) * LDQ + kf * 16], LDQ);
#pragma unroll
                for (int j = 0; j < 4; j++)
                    wmma::mma_sync(sacc[i][j], fa, fbT[j], sacc[i][j]);
            }
        }

        // ---- exp + fp16 tile in smem ----
#pragma unroll
        for (int i = 0; i < 2; i++)
#pragma unroll
            for (int j = 0; j < 4; j++) {
#pragma unroll
                for (int e = 0; e < 8; e++)
                    sacc[i][j].x[e] = __expf(sacc[i][j].x[e] * 0.125f);
                wmma::store_matrix_sync(st, sacc[i][j], 20, wmma::mem_row_major);
                __syncwarp();
                const int r  = lane >> 1;
                const int c0 = (lane & 1) * 8;
                __half2 hp[4];
#pragma unroll
                for (int k2 = 0; k2 < 4; k2++)
                    hp[k2] = __floats2half2_rn(st[r * 20 + c0 + 2 * k2],
                                               st[r * 20 + c0 + 2 * k2 + 1]);
                uint4 u;
                memcpy(&u, hp, 16);
                *reinterpret_cast<uint4*>(&S16[(wm0 + i * 16 + r) * LDS + wn0 + j * 16 + c0]) = u;
                __syncwarp();
            }
        __syncthreads();

        // ---- Z partials + gmem copy of expS tile ----
        {
            const int r = tid >> 1, hf = tid & 1;
            const __half2* p2 = reinterpret_cast<const __half2*>(&S16[r * LDS + hf * 64]);
            float s = 0.0f;
#pragma unroll
            for (int i = 0; i < 32; i++) {
                const float2 f = __half22float2(p2[i]);
                s += f.x + f.y;
            }
            psum[tid] = s;
        }
#pragma unroll
        for (int idx = tid; idx < 2048; idx += 256) {
            const int r = idx >> 4, c = idx & 15;
            *reinterpret_cast<uint4*>(Erow + (size_t)r * SS + kt * 128 + c * 8) =
                *reinterpret_cast<const uint4*>(&S16[r * LDS + c * 8]);
        }
        __syncthreads();
        if (tid < 128) Zs[tid] += psum[2 * tid] + psum[2 * tid + 1];

        // ---- U += expS @ V (128x64, K=128) ----
#pragma unroll
        for (int kf = 0; kf < 8; kf++) {
#pragma unroll
            for (int j = 0; j < 2; j++)
                wmma::load_matrix_sync(fbN[j], &Vst[(kf * 16) * LDQ + wnU + j * 16], LDQ);
#pragma unroll
            for (int i = 0; i < 2; i++) {
                wmma::load_matrix_sync(fa, &S16[(wm0 + i * 16) * LDS + kf * 16], LDS);
#pragma unroll
                for (int j = 0; j < 2; j++)
                    wmma::mma_sync(uacc[i][j], fa, fbN[j], uacc[i][j]);
            }
        }
        __syncthreads();
    }

    if (tid < 128) {
        const float iz = 1.0f / Zs[tid];
        Zs[tid] = iz;
        invz[(size_t)bh * SS + q0 + tid] = iz;
    }
    __syncthreads();

#pragma unroll
    for (int i = 0; i < 2; i++)
#pragma unroll
        for (int j = 0; j < 2; j++) {
            wmma::store_matrix_sync(st, uacc[i][j], 20, wmma::mem_row_major);
            __syncwarp();
            const int r  = lane >> 1;
            const int c0 = (lane & 1) * 8;
            const int row = wm0 + i * 16 + r;
            const float iz = Zs[row];
            const size_t base = ((size_t)b * SS + q0 + row) * DD + h * DKK + wnU + j * 16 + c0;
            __half2 hh[4];
#pragma unroll
            for (int k2 = 0; k2 < 4; k2++)
                hh[k2] = __floats2half2_rn(st[r * 20 + c0 + 2 * k2] * iz,
                                           st[r * 20 + c0 + 2 * k2 + 1] * iz);
            uint4 uh;
            memcpy(&uh, hh, 16);
            *reinterpret_cast<uint4*>(ch + base) = uh;
            __syncwarp();
        }
}

static constexpr size_t FUSED_SMEM =
    ((size_t)128 * 72 + 2 * 128 * 72 + 2 * 128 * 72 + 128 * 136) * 2 +
    ((size_t)8 * 16 * 20 + 256 + 128) * 4;

// ---------------------------------------------------------------------------
// Head mean: out[b,q,k] = (1/16) sum_h expS[b,h,q,k] * invZ[b,h,q]
// ---------------------------------------------------------------------------
__global__ __launch_bounds__(256) void mean_h(const half* __restrict__ expsc,
                                              const float* __restrict__ invz,
                                              float* __restrict__ outw)
{
    const int q = blockIdx.x & (SS - 1);
    const int b = blockIdx.x >> 11;
    const int tid = threadIdx.x;

    float acc[8] = {0, 0, 0, 0, 0, 0, 0, 0};
#pragma unroll
    for (int h = 0; h < HH; h++) {
        const size_t off = (((size_t)(b * HH + h)) * SS + q) * SS;
        const float iz = __ldg(invz + (size_t)(b * HH + h) * SS + q);
        const uint4 u = reinterpret_cast<const uint4*>(expsc + off)[tid];
        __half2 h2[4];
        memcpy(h2, &u, 16);
#pragma unroll
        for (int k2 = 0; k2 < 4; k2++) {
            const float2 f = __half22float2(h2[k2]);
            acc[2 * k2]     += f.x * iz;
            acc[2 * k2 + 1] += f.y * iz;
        }
    }
    float* o = outw + ((size_t)b * SS + q) * SS + (size_t)tid * 8;
    *reinterpret_cast<float4*>(o)     = make_float4(acc[0] * (1.0f / HH), acc[1] * (1.0f / HH),
                                                    acc[2] * (1.0f / HH), acc[3] * (1.0f / HH));
    *reinterpret_cast<float4*>(o + 4) = make_float4(acc[4] * (1.0f / HH), acc[5] * (1.0f / HH),
                                                    acc[6] * (1.0f / HH), acc[7] * (1.0f / HH));
}

// ---------------------------------------------------------------------------
extern "C" void kernel_launch(void* const* d_in, const int* in_sizes, int n_in,
                              void* d_out, int out_size)
{
    const float* act[3] = {nullptr, nullptr, nullptr};
    const float* wgt[4] = {nullptr, nullptr, nullptr, nullptr};
    const float* bia[4] = {nullptr, nullptr, nullptr, nullptr};
    int na = 0, nw = 0, nb = 0;
    for (int i = 0; i < n_in; i++) {
        const int sz = in_sizes[i];
        if (sz == (int)NACT)      { if (na < 3) act[na++] = (const float*)d_in[i]; }
        else if (sz == (int)NW)   { if (nw < 4) wgt[nw++] = (const float*)d_in[i]; }
        else if (sz == DD)        { if (nb < 4) bia[nb++] = (const float*)d_in[i]; }
    }
    const float* query = act[0];
    const float* key   = act[1];
    const float* value = act[2];
    const float *bq = bia[0], *bk = bia[1], *bv = bia[2], *bo = bia[3];

    float* out_proj = (float*)d_out;
    float* out_attn = (float*)d_out + NACT;

    half *qh, *kh, *vh, *Wqh, *Wkh, *Wvh, *Woh, *Wol;
    half *yqh, *ykh, *yvh, *ch, *es;
    float *iz;
    cudaGetSymbolAddress((void**)&qh, g_qh);
    cudaGetSymbolAddress((void**)&kh, g_kh);
    cudaGetSymbolAddress((void**)&vh, g_vh);
    cudaGetSymbolAddress((void**)&Wqh, g_Wqh);
    cudaGetSymbolAddress((void**)&Wkh, g_Wkh);
    cudaGetSymbolAddress((void**)&Wvh, g_Wvh);
    cudaGetSymbolAddress((void**)&Woh, g_Woh);
    cudaGetSymbolAddress((void**)&Wol, g_Wol);
    cudaGetSymbolAddress((void**)&yqh, g_yqh);
    cudaGetSymbolAddress((void**)&ykh, g_ykh);
    cudaGetSymbolAddress((void**)&yvh, g_yvh);
    cudaGetSymbolAddress((void**)&ch, g_ch);
    cudaGetSymbolAddress((void**)&es, g_es);
    cudaGetSymbolAddress((void**)&iz, g_iz);

    cudaFuncSetAttribute(proj_h, cudaFuncAttributeMaxDynamicSharedMemorySize, (int)SM_PROJ);
    cudaFuncSetAttribute(gemm_out, cudaFuncAttributeMaxDynamicSharedMemorySize, (int)SM_OUT);
    cudaFuncSetAttribute(fused_attn, cudaFuncAttributeMaxDynamicSharedMemorySize, (int)FUSED_SMEM);

    // 0: converts (q,k,v and Wq,Wk,Wv hi-only) + Wo split
    {
        const int n1 = (int)(NACT / 4), n2 = (int)(NW / 4);
        dim3 g1((n1 + 255) / 256, 3);
        conv3_v4<<<g1, 256>>>((const float4*)query, (const float4*)key, (const float4*)value,
                              (uint2*)qh, (uint2*)kh, (uint2*)vh, n1);
        dim3 g2((n2 + 255) / 256, 3);
        conv3_v4<<<g2, 256>>>((const float4*)wgt[0], (const float4*)wgt[1], (const float4*)wgt[2],
                              (uint2*)Wqh, (uint2*)Wkh, (uint2*)Wvh, n2);
        split_f32_v4<<<(n2 + 255) / 256, 256>>>((const float4*)wgt[3], (uint2*)Woh, (uint2*)Wol, n2);
    }

    // 1: all three projections in one launch (pure fp16, 3-stage pipeline)
    {
        dim3 gp(DD / 128, (BB * SS) / 128, 3);
        proj_h<<<gp, 256, SM_PROJ>>>(qh, kh, vh, Wqh, Wkh, Wvh, bq, bk, bv, yqh, ykh, yvh);
    }

    // 2: fused attention (QK^T -> exp -> PV), ctx hi-only
    {
        dim3 ga(SS / 128, BB * HH, 1);
        fused_attn<<<ga, 256, FUSED_SMEM>>>(yqh, ykh, yvh, es, iz, ch);
    }

    // 3: head-mean of attention weights
    mean_h<<<BB * SS, 256>>>(es, iz, out_attn);

    // 4: out = ctx @ Wo^T + bo (A hi-only, B split, 2 mmas)
    {
        dim3 gp(DD / 128, (BB * SS) / 128, 1);
        gemm_out<<<gp, 256, SM_OUT>>>(ch, Woh, Wol, bo, out_proj);
    }
}